// round 12
// baseline (speedup 1.0000x reference)
#include <cuda_runtime.h>
#include <stdint.h>
#include <math.h>

#define NPOS 128          // positions per block (1 per thread)
#define THREADS 128
#define CH 84
#define L_SEQ 8192
#define B_SEQ 16

// dynamic smem layout (float offsets)
#define AB_OFF 0          // 64 dims * 16 * 2 = 2048 (15 states + zero pad)
#define SB_OFF 2048       // class emit [s][q] 16*16 = 256
#define K_OFF  2304       // 16
#define NB_OFF 2320       // 132 float4 halo = 528 (doubles as prep scratch)
#define XS_OFF 2848       // 128 * 84 tile = 10752
#define SMEM_FLOATS 13600
#define SMEM_BYTES (SMEM_FLOATS * 4)   // 54400 B -> 4 blocks/SM

__device__ __forceinline__ float ex2(float x) {
    float r;
    asm("ex2.approx.ftz.f32 %0, %1;" : "=f"(r) : "f"(x));
    return r;
}
__device__ __forceinline__ void cp_async16(unsigned int saddr, const void* gaddr) {
    asm volatile("cp.async.cg.shared.global [%0], [%1], 16;" :: "r"(saddr), "l"(gaddr));
}

__device__ __forceinline__ void codon_full(const float4* nbp, float* fullv) {
    float4 m2 = nbp[0], m1 = nbp[1], c0 = nbp[2], q1 = nbp[3], q2 = nbp[4];
    float S_c0 = c0.x + c0.y + c0.z + c0.w;
    float S_q1 = q1.x + q1.y + q1.z + q1.w;
    float S_q2 = q2.x + q2.y + q2.z + q2.w;
    float S_m1 = m1.x + m1.y + m1.z + m1.w;
    float S_m2 = m2.x + m2.y + m2.z + m2.w;
    float L_any   = S_c0 * S_q1 * S_q2 * (1.f / 64.f);
    float L_start = c0.x * q1.w * q2.z;           // ATG
    float L_ib    = 0.25f * S_c0 * q1.z * q2.w;   // NGT
    float Pall = S_m2 * S_m1 * S_c0;
    float tAA = m1.x * c0.x, tAG = m1.x * c0.z, tGA = m1.z * c0.x;
    float R_ns   = (Pall - m2.w * (tAA + tAG + tGA)) * (1.f / 61.f);
    float R_any  = Pall * (1.f / 64.f);
    float R_iep  = m2.x * m1.z * 0.25f * S_c0;    // AGN
    float R_stop = m2.w * (0.34f * tAA + 0.33f * tAG + 0.33f * tGA);
    fullv[0] = 1.f; fullv[1] = 1.f; fullv[2] = 1.f;
    fullv[3] = 1.f; fullv[4] = 1.f; fullv[5] = 1.f;
    fullv[6]  = L_any * R_ns;
    fullv[7]  = L_start * R_any;
    fullv[8]  = L_ib * R_any;
    fullv[9]  = L_ib * R_ns;
    fullv[10] = L_ib * R_any;
    fullv[11] = L_any * R_iep;
    fullv[12] = L_any * R_iep;
    fullv[13] = L_any * R_iep;
    fullv[14] = L_any * R_stop;
}

// One MVN dim; cf advances one dim (8 float4).
__device__ __forceinline__ void proc_dim(const float4*& cf, float x, float* a) {
    float x2 = x * x;
#pragma unroll
    for (int h = 0; h < 7; h++) {
        float4 c = cf[h];
        a[2*h]   = fmaf(c.x, x2, fmaf(c.y, x, a[2*h]));
        a[2*h+1] = fmaf(c.z, x2, fmaf(c.w, x, a[2*h+1]));
    }
    float4 c14 = cf[7];   // .x/.y real (state 14); .z/.w zero pad
    a[14] = fmaf(c14.x, x2, fmaf(c14.y, x, a[14]));
    cf += 8;
}

__global__ void __launch_bounds__(THREADS)
emit_kernel(const float* __restrict__ inputs,
            const float* __restrict__ eh,
            const float* __restrict__ ek,
            const float* __restrict__ eek,
            float* __restrict__ out) {
    extern __shared__ float sh[];
    const int tid = threadIdx.x;
    const int b  = blockIdx.x >> 6;
    const int p0 = (blockIdx.x & 63) << 7;
    const float* gbase = inputs + (size_t)(b * L_SEQ + p0) * CH;

    // ---- phase 0: async tile stage (coalesced) ----
    {
        unsigned int sbase = (unsigned int)__cvta_generic_to_shared(sh + XS_OFF);
        const float4* in4 = (const float4*)gbase;
#pragma unroll 3
        for (int i = tid; i < NPOS * CH / 4; i += THREADS)
            cp_async16(sbase + i * 16, in4 + i);
        asm volatile("cp.async.commit_group;");
    }

    // ---- inline prep (overlaps async copy) ----
    const float kscale = (float)(1.4426950408889634 / 100.0); // log2(e)/TEMP
    const float basec  = (float)log(expm1(sqrt(0.05)));
    const float cconst = (float)(0.5 * 64.0 * log(2.0 * M_PI));

    if (tid < 15) {               // softmax rows -> SB[s][q] = B[q][s]
        int q = tid;
        float m = -1e30f;
        for (int s = 0; s < 15; s++) m = fmaxf(m, ek[q * 15 + s]);
        float e[15]; float sum = 0.f;
        for (int s = 0; s < 15; s++) { e[s] = expf(ek[q * 15 + s] - m); sum += e[s]; }
        float inv = 1.f / sum;
        for (int s = 0; s < 15; s++) sh[SB_OFF + s * 16 + q] = e[s] * inv;
    }
    if (tid == 15) {
        for (int s = 0; s < 16; s++) sh[SB_OFF + s * 16 + 15] = 0.f;
    }
    if (tid < 120) {              // MVN coefficients, thread = (state, dim-octet)
        int s = tid >> 3, g = tid & 7;
        float Cp = 0.f, ldp = 0.f;
        for (int k = 0; k < 8; k++) {
            int d = g * 8 + k;
            float mu = eek[s * 128 + d];
            float v  = eek[s * 128 + 64 + d] + basec;
            float sp = (v > 20.f) ? v : log1pf(expf(v));
            float is2 = 1.f / (sp * sp);
            sh[AB_OFF + d * 32 + s * 2 + 0] = -0.5f * is2 * kscale;  // A'
            sh[AB_OFF + d * 32 + s * 2 + 1] = mu * is2 * kscale;     // B'
            Cp  = fmaf(mu * mu, is2, Cp);
            ldp += logf(sp);
        }
        sh[NB_OFF + tid * 2 + 0] = Cp;   // scratch (halo region, rebuilt later)
        sh[NB_OFF + tid * 2 + 1] = ldp;
    } else if (tid >= 120 && tid < 128) {
        int g = tid - 120;        // zero-pad state-15 slots (c14.z/.w)
        for (int k = 0; k < 8; k++) {
            int d = g * 8 + k;
            sh[AB_OFF + d * 32 + 30] = 0.f;
            sh[AB_OFF + d * 32 + 31] = 0.f;
        }
    }
    __syncthreads();
    if (tid < 15) {
        float C = 0.f, ld = 0.f;
        for (int g = 0; g < 8; g++) {
            C  += sh[NB_OFF + (tid * 8 + g) * 2 + 0];
            ld += sh[NB_OFF + (tid * 8 + g) * 2 + 1];
        }
        sh[K_OFF + tid] = (-0.5f * C - ld - cconst) * kscale;
    }
    asm volatile("cp.async.wait_group 0;");
    __syncthreads();

    // ---- nucleotide halo buffer (interior rows from tile) ----
    float4* nb = (float4*)(sh + NB_OFF);
    for (int i = tid; i < NPOS + 4; i += THREADS) {
        int gl = p0 + i - 2;
        float4 nv;
        if (gl >= 0 && gl < L_SEQ) {
            int li = i - 2;
            const float* nr;
            if (li >= 0 && li < NPOS) nr = sh + XS_OFF + li * CH;
            else                      nr = inputs + (size_t)(b * L_SEQ + gl) * CH;
            float n0 = nr[79];
            float4 f = *(const float4*)(nr + 80);   // ch 80..83
            nv = make_float4(fmaf(0.25f, f.w, n0),  fmaf(0.25f, f.w, f.x),
                             fmaf(0.25f, f.w, f.y), fmaf(0.25f, f.w, f.z));
        } else {
            nv = make_float4(0.25f, 0.25f, 0.25f, 0.25f);
        }
        nb[i] = nv;
    }
    __syncthreads();

    float* row = sh + XS_OFF + tid * CH;

    // ====== phase A: class matvec + codon + hints -> staged into row ======
    float x15;
    {
        float cls[16];
#pragma unroll
        for (int j = 0; j < 4; j++)
            *(float4*)(cls + 4 * j) = *(const float4*)(row + 4 * j);
        x15 = cls[15];
        float ca[16];
#pragma unroll
        for (int q = 0; q < 16; q++) ca[q] = 0.f;
        const float4* br = (const float4*)(sh + SB_OFF);
#pragma unroll 3
        for (int s = 0; s < 15; s++) {
            float xs = cls[s];
#pragma unroll
            for (int h = 0; h < 4; h++) {
                float4 bv = br[h];
                ca[4*h+0] = fmaf(bv.x, xs, ca[4*h+0]);
                ca[4*h+1] = fmaf(bv.y, xs, ca[4*h+1]);
                ca[4*h+2] = fmaf(bv.z, xs, ca[4*h+2]);
                ca[4*h+3] = fmaf(bv.w, xs, ca[4*h+3]);
            }
            br += 4;
        }
        float fullv[15];
        codon_full(nb + tid, fullv);
        const int gl = p0 + tid;
        const float* hp = nullptr;
        if (gl == 0)              hp = eh + b * 30;
        else if (gl == L_SEQ - 1) hp = eh + b * 30 + 15;
#pragma unroll
        for (int q = 0; q < 15; q++) {
            float o = ca[q] * fullv[q];
            if (hp) o *= hp[q];
            row[q] = o;       // class slots dead after this phase
        }
    }

    // ====== phase B: MVN exponents (15 states, scalar FFMA) ======
    float a[15];
#pragma unroll
    for (int q = 0; q < 15; q++) a[q] = sh[K_OFF + q];

    const float4* cf = (const float4*)(sh + AB_OFF);
    proc_dim(cf, x15, a);                         // dim 0 = channel 15

    const float4* gp = (const float4*)(row + 16); // channels 16..79
#pragma unroll 2
    for (int j = 0; j < 15; j++) {                // dims 1..60
        float4 v = gp[0];
        proc_dim(cf, v.x, a);
        proc_dim(cf, v.y, a);
        proc_dim(cf, v.z, a);
        proc_dim(cf, v.w, a);
        gp += 1;
    }
    {
        float4 t = gp[0];                         // ch 76..79 -> dims 61..63
        proc_dim(cf, t.x, a);
        proc_dim(cf, t.y, a);
        proc_dim(cf, t.z, a);
    }

    // finalize: multiply staged (class*codon*hint) by exp2(exponent)
#pragma unroll
    for (int q = 0; q < 15; q++)
        row[q] *= ex2(a[q]);
    __syncthreads();

    // coalesced flush (incremental pos/q, no divisions)
    float* og = out + (size_t)(b * L_SEQ + p0) * 15;
    int pos = tid / 15;
    int q   = tid - pos * 15;
#pragma unroll 5
    for (int i = tid; i < NPOS * 15; i += THREADS) {
        og[i] = sh[XS_OFF + pos * CH + q];
        pos += 8; q += 8;
        if (q >= 15) { q -= 15; pos += 1; }
    }
}

extern "C" void kernel_launch(void* const* d_in, const int* in_sizes, int n_in,
                              void* d_out, int out_size) {
    const float *inp = nullptr, *eh = nullptr, *ek = nullptr, *eek = nullptr;
    for (int i = 0; i < n_in; i++) {
        switch (in_sizes[i]) {
            case 11010048: inp = (const float*)d_in[i]; break; // inputs
            case 480:      eh  = (const float*)d_in[i]; break; // end_hints
            case 225:      ek  = (const float*)d_in[i]; break; // emission_kernel
            case 1920:     eek = (const float*)d_in[i]; break; // embedding_emission_kernel
        }
    }
    float* out = (float*)d_out;

    cudaFuncSetAttribute(emit_kernel, cudaFuncAttributeMaxDynamicSharedMemorySize,
                         SMEM_BYTES);

    emit_kernel<<<(B_SEQ * L_SEQ) / NPOS, THREADS, SMEM_BYTES>>>(inp, eh, ek, eek, out);
}

// round 13
// speedup vs baseline: 1.1863x; 1.1863x over previous
#include <cuda_runtime.h>
#include <stdint.h>
#include <math.h>

#define NPOS 256          // positions per block
#define THREADS 128       // 2 positions per thread
#define CH 84
#define L_SEQ 8192
#define B_SEQ 16

// smem layout (float offsets)
#define AB_OFF 0          // 64 dims * 16 states * 2 (A,B)     = 2048
#define SB_OFF 2048       // class emit, [s][q] 16*16          = 256
#define K_OFF  2304       // 16
#define NB_OFF 2320       // 260 float4 nuc halo               = 1040
#define XS_OFF 3360       // 256 * 84 tile                     = 21504
#define SMEM_FLOATS 24864
#define SMEM_BYTES (SMEM_FLOATS * 4)

typedef unsigned long long ull;

__device__ __forceinline__ ull fma2(ull a, ull b, ull c) {
    ull d;
    asm("fma.rn.f32x2 %0, %1, %2, %3;" : "=l"(d) : "l"(a), "l"(b), "l"(c));
    return d;
}
__device__ __forceinline__ ull pk2(float lo, float hi) {
    ull d;
    asm("mov.b64 %0, {%1, %2};" : "=l"(d) : "f"(lo), "f"(hi));
    return d;
}
__device__ __forceinline__ void upk2(float& lo, float& hi, ull v) {
    asm("mov.b64 {%0, %1}, %2;" : "=f"(lo), "=f"(hi) : "l"(v));
}
__device__ __forceinline__ float ex2(float x) {
    float r;
    asm("ex2.approx.ftz.f32 %0, %1;" : "=f"(r) : "f"(x));
    return r;
}
__device__ __forceinline__ void cp_async16(unsigned int saddr, const void* gaddr) {
    asm volatile("cp.async.cg.shared.global [%0], [%1], 16;" :: "r"(saddr), "l"(gaddr));
}

// codon factor for one position; nbp points at nb entry for (global pos - 2)
__device__ __forceinline__ void codon_full(const float4* nbp, float* fullv) {
    float4 m2 = nbp[0], m1 = nbp[1], c0 = nbp[2], q1 = nbp[3], q2 = nbp[4];
    float S_c0 = c0.x + c0.y + c0.z + c0.w;
    float S_q1 = q1.x + q1.y + q1.z + q1.w;
    float S_q2 = q2.x + q2.y + q2.z + q2.w;
    float S_m1 = m1.x + m1.y + m1.z + m1.w;
    float S_m2 = m2.x + m2.y + m2.z + m2.w;
    float L_any   = S_c0 * S_q1 * S_q2 * (1.f / 64.f);
    float L_start = c0.x * q1.w * q2.z;           // ATG
    float L_ib    = 0.25f * S_c0 * q1.z * q2.w;   // NGT
    float Pall = S_m2 * S_m1 * S_c0;
    float tAA = m1.x * c0.x, tAG = m1.x * c0.z, tGA = m1.z * c0.x;
    float R_ns   = (Pall - m2.w * (tAA + tAG + tGA)) * (1.f / 61.f);
    float R_any  = Pall * (1.f / 64.f);
    float R_iep  = m2.x * m1.z * 0.25f * S_c0;    // AGN
    float R_stop = m2.w * (0.34f * tAA + 0.33f * tAG + 0.33f * tGA);
    fullv[0] = 1.f; fullv[1] = 1.f; fullv[2] = 1.f;
    fullv[3] = 1.f; fullv[4] = 1.f; fullv[5] = 1.f;
    fullv[6]  = L_any * R_ns;
    fullv[7]  = L_start * R_any;
    fullv[8]  = L_ib * R_any;
    fullv[9]  = L_ib * R_ns;
    fullv[10] = L_ib * R_any;
    fullv[11] = L_any * R_iep;
    fullv[12] = L_any * R_iep;
    fullv[13] = L_any * R_iep;
    fullv[14] = L_any * R_stop;
}

// One MVN dim for both positions (packed); cdim advances one dim (8 u64x2).
__device__ __forceinline__ void proc_dim_pk(const ulonglong2*& cdim,
                                            float xA, float xB,
                                            ull* acc0, ull* acc1) {
    ull xa = pk2(xA * xA, xA);
    ull xb = pk2(xB * xB, xB);
#pragma unroll
    for (int h = 0; h < 8; h++) {
        ulonglong2 cv = cdim[h];
        acc0[2*h]   = fma2(cv.x, xa, acc0[2*h]);
        acc0[2*h+1] = fma2(cv.y, xa, acc0[2*h+1]);
        acc1[2*h]   = fma2(cv.x, xb, acc1[2*h]);
        acc1[2*h+1] = fma2(cv.y, xb, acc1[2*h+1]);
    }
    cdim += 8;
}

__global__ void __launch_bounds__(THREADS)
emit_kernel(const float* __restrict__ inputs,
            const float* __restrict__ eh,
            const float* __restrict__ ek,
            const float* __restrict__ eek,
            float* __restrict__ out) {
    extern __shared__ float sm[];
    const int tid = threadIdx.x;
    const int b  = blockIdx.x >> 5;
    const int p0 = (blockIdx.x & 31) << 8;

    // ---------------- phase 1: async tile load + inline prep ----------------
    const float4* in4 = (const float4*)(inputs + (size_t)(b * L_SEQ + p0) * CH);
    {
        unsigned int sbase = (unsigned int)__cvta_generic_to_shared(sm + XS_OFF);
#pragma unroll 6
        for (int i = tid; i < NPOS * CH / 4; i += THREADS)
            cp_async16(sbase + i * 16, in4 + i);
        asm volatile("cp.async.commit_group;");
    }

    const float kscale = (float)(1.4426950408889634 / 100.0); // log2(e)/TEMP
    const float basec  = (float)log(expm1(sqrt(0.05)));
    const float cconst = (float)(0.5 * 64.0 * log(2.0 * M_PI));

    // softmax rows of emission kernel -> SB[s][q]
    if (tid < 15) {
        int q = tid;
        float m = -1e30f;
        for (int s = 0; s < 15; s++) m = fmaxf(m, ek[q * 15 + s]);
        float e[15]; float sum = 0.f;
        for (int s = 0; s < 15; s++) { e[s] = expf(ek[q * 15 + s] - m); sum += e[s]; }
        float inv = 1.f / sum;
        for (int s = 0; s < 15; s++) sm[SB_OFF + s * 16 + q] = e[s] * inv;
    }
    if (tid == 15) {  // zero-pad column q=15 of SB
        for (int s = 0; s < 16; s++) sm[SB_OFF + s * 16 + 15] = 0.f;
    }
    // MVN coefficients: thread t = s*8+g handles dims 8g..8g+7 of state s
    if (tid < 120) {
        int s = tid >> 3, g = tid & 7;
        float Cp = 0.f, ldp = 0.f;
        for (int k = 0; k < 8; k++) {
            int d = g * 8 + k;
            float mu = eek[s * 128 + d];
            float v  = eek[s * 128 + 64 + d] + basec;
            float sp = (v > 20.f) ? v : log1pf(expf(v));
            float is2 = 1.f / (sp * sp);
            sm[AB_OFF + d * 32 + s * 2 + 0] = -0.5f * is2 * kscale;
            sm[AB_OFF + d * 32 + s * 2 + 1] = mu * is2 * kscale;
            Cp  = fmaf(mu * mu, is2, Cp);
            ldp += logf(sp);
        }
        sm[NB_OFF + tid * 2 + 0] = Cp;   // scratch (NB region, rebuilt later)
        sm[NB_OFF + tid * 2 + 1] = ldp;
    } else if (tid >= 120 && tid < 128) {
        // zero-pad state 15 coefficients
        int g = tid - 120;
        for (int k = 0; k < 8; k++) {
            int d = g * 8 + k;
            sm[AB_OFF + d * 32 + 30] = 0.f;
            sm[AB_OFF + d * 32 + 31] = 0.f;
        }
    }
    __syncthreads();
    if (tid < 15) {
        float C = 0.f, ld = 0.f;
        for (int g = 0; g < 8; g++) {
            C  += sm[NB_OFF + (tid * 8 + g) * 2 + 0];
            ld += sm[NB_OFF + (tid * 8 + g) * 2 + 1];
        }
        sm[K_OFF + tid] = (-0.5f * C - ld - cconst) * kscale;
    } else if (tid == 15) {
        sm[K_OFF + 15] = 0.f;
    }
    asm volatile("cp.async.wait_group 0;");
    __syncthreads();

    // ---------------- phase 2: nucleotide halo buffer ----------------
    float4* nb = (float4*)(sm + NB_OFF);
    for (int i = tid; i < NPOS + 4; i += THREADS) {
        int gl = p0 + i - 2;
        float4 nv;
        if (gl >= 0 && gl < L_SEQ) {
            int li = gl - p0;
            const float* nr;
            if (li >= 0 && li < NPOS) nr = sm + XS_OFF + li * CH + 79;
            else                      nr = inputs + (size_t)(b * L_SEQ + gl) * CH + 79;
            float n4 = nr[4];
            nv = make_float4(fmaf(0.25f, n4, nr[0]), fmaf(0.25f, n4, nr[1]),
                             fmaf(0.25f, n4, nr[2]), fmaf(0.25f, n4, nr[3]));
        } else {
            nv = make_float4(0.25f, 0.25f, 0.25f, 0.25f);
        }
        nb[i] = nv;
    }
    __syncthreads();

    // ---------------- phase 3: per-thread compute (2 positions) ----------------
    float* rowA = sm + XS_OFF + tid * CH;
    float* rowB = rowA + 128 * CH;

    // MVN accumulators: packed (sum A*x^2, sum B*x) per state, init (K,0)
    ull acc0[16], acc1[16];
#pragma unroll
    for (int q = 0; q < 16; q++) {
        float Kq = sm[K_OFF + q];
        acc0[q] = pk2(Kq, 0.f);
        acc1[q] = pk2(Kq, 0.f);
    }

    float x15A = rowA[15], x15B = rowB[15];
    const ulonglong2* cdim = (const ulonglong2*)(sm + AB_OFF);
    proc_dim_pk(cdim, x15A, x15B, acc0, acc1);     // dim 0 = channel 15

    const float4* gp0 = (const float4*)(rowA + 16);   // channels 16..79
    const float4* gp1 = (const float4*)(rowB + 16);
#pragma unroll 3
    for (int j = 0; j < 15; j++) {      // dims 1..60
        float4 v0 = gp0[0];
        float4 v1 = gp1[0];
        proc_dim_pk(cdim, v0.x, v1.x, acc0, acc1);
        proc_dim_pk(cdim, v0.y, v1.y, acc0, acc1);
        proc_dim_pk(cdim, v0.z, v1.z, acc0, acc1);
        proc_dim_pk(cdim, v0.w, v1.w, acc0, acc1);
        gp0 += 1; gp1 += 1;
    }
    {
        float4 t0 = gp0[0], t1 = gp1[0];  // channels 76..79 -> dims 61..63
        proc_dim_pk(cdim, t0.x, t1.x, acc0, acc1);
        proc_dim_pk(cdim, t0.y, t1.y, acc0, acc1);
        proc_dim_pk(cdim, t0.z, t1.z, acc0, acc1);
    }

    float eA[15], eB[15];
#pragma unroll
    for (int q = 0; q < 15; q++) {
        float lo, hi;
        upk2(lo, hi, acc0[q]); eA[q] = ex2(lo + hi);
        upk2(lo, hi, acc1[q]); eB[q] = ex2(lo + hi);
    }

    // class matvec: packed over state pairs (pointer-walked)
    ull ca[8], cb[8];
#pragma unroll
    for (int h = 0; h < 8; h++) { ca[h] = 0ull; cb[h] = 0ull; }
    {
        const ulonglong2* br = (const ulonglong2*)(sm + SB_OFF);
#pragma unroll 3
        for (int s = 0; s < 15; s++) {
            ulonglong2 b01 = br[0], b23 = br[1], b45 = br[2], b67 = br[3];
            float cvA = rowA[s], cvB = rowB[s];
            ull cpA = pk2(cvA, cvA), cpB = pk2(cvB, cvB);
            ca[0] = fma2(b01.x, cpA, ca[0]); ca[1] = fma2(b01.y, cpA, ca[1]);
            ca[2] = fma2(b23.x, cpA, ca[2]); ca[3] = fma2(b23.y, cpA, ca[3]);
            ca[4] = fma2(b45.x, cpA, ca[4]); ca[5] = fma2(b45.y, cpA, ca[5]);
            ca[6] = fma2(b67.x, cpA, ca[6]); ca[7] = fma2(b67.y, cpA, ca[7]);
            cb[0] = fma2(b01.x, cpB, cb[0]); cb[1] = fma2(b01.y, cpB, cb[1]);
            cb[2] = fma2(b23.x, cpB, cb[2]); cb[3] = fma2(b23.y, cpB, cb[3]);
            cb[4] = fma2(b45.x, cpB, cb[4]); cb[5] = fma2(b45.y, cpB, cb[5]);
            cb[6] = fma2(b67.x, cpB, cb[6]); cb[7] = fma2(b67.y, cpB, cb[7]);
            br += 4;
        }
    }
    float clA[16], clB[16];
#pragma unroll
    for (int h = 0; h < 8; h++) {
        upk2(clA[2*h], clA[2*h+1], ca[h]);
        upk2(clB[2*h], clB[2*h+1], cb[h]);
    }

    // codon factors
    float fullA[15], fullB[15];
    codon_full(nb + tid, fullA);
    codon_full(nb + tid + 128, fullB);

    // end hints
    const int glA = p0 + tid;
    const int glB = glA + 128;
    const float* hpA = nullptr;
    const float* hpB = nullptr;
    if (glA == 0)              hpA = eh + b * 30;
    else if (glA == L_SEQ - 1) hpA = eh + b * 30 + 15;
    if (glB == 0)              hpB = eh + b * 30;
    else if (glB == L_SEQ - 1) hpB = eh + b * 30 + 15;

    // write results into own rows (fully consumed), then coalesced flush
#pragma unroll
    for (int q = 0; q < 15; q++) {
        float oA = clA[q] * eA[q] * fullA[q];
        float oB = clB[q] * eB[q] * fullB[q];
        if (hpA) oA *= hpA[q];
        if (hpB) oB *= hpB[q];
        rowA[q] = oA;
        rowB[q] = oB;
    }
    __syncthreads();

    // coalesced flush (incremental pos/q, no divisions)
    float* og = out + (size_t)(b * L_SEQ + p0) * 15;
    int pos = tid / 15;
    int q   = tid - pos * 15;
#pragma unroll 6
    for (int i = tid; i < NPOS * 15; i += THREADS) {
        og[i] = sm[XS_OFF + pos * CH + q];
        pos += 8; q += 8;
        if (q >= 15) { q -= 15; pos += 1; }
    }
}

extern "C" void kernel_launch(void* const* d_in, const int* in_sizes, int n_in,
                              void* d_out, int out_size) {
    const float *inp = nullptr, *eh = nullptr, *ek = nullptr, *eek = nullptr;
    for (int i = 0; i < n_in; i++) {
        switch (in_sizes[i]) {
            case 11010048: inp = (const float*)d_in[i]; break; // inputs
            case 480:      eh  = (const float*)d_in[i]; break; // end_hints
            case 225:      ek  = (const float*)d_in[i]; break; // emission_kernel
            case 1920:     eek = (const float*)d_in[i]; break; // embedding_emission_kernel
        }
    }
    float* out = (float*)d_out;

    cudaFuncSetAttribute(emit_kernel, cudaFuncAttributeMaxDynamicSharedMemorySize,
                         SMEM_BYTES);

    emit_kernel<<<(B_SEQ * L_SEQ) / NPOS, THREADS, SMEM_BYTES>>>(inp, eh, ek, eek, out);
}

// round 17
// speedup vs baseline: 1.2653x; 1.0666x over previous
#include <cuda_runtime.h>
#include <stdint.h>
#include <math.h>

#define NPOS 256          // positions per block
#define THREADS 128       // 2 positions per thread
#define CH 84
#define L_SEQ 8192
#define B_SEQ 16

// smem layout (float offsets)
#define AB_OFF 0          // 64 dims * 32 floats: [d][A_s x16][B_s x16] = 2048
#define SB_OFF 2048       // class emit, [s][q] 16*16 = 256
#define K_OFF  2304       // 16 (16B aligned)
#define NB_OFF 2320       // 260 float4 nuc halo = 1040
#define XS_OFF 3360       // 256 * 84 tile = 21504
#define SMEM_FLOATS 24864
#define SMEM_BYTES (SMEM_FLOATS * 4)

typedef unsigned long long ull;

__device__ __forceinline__ ull fma2(ull a, ull b, ull c) {
    ull d;
    asm("fma.rn.f32x2 %0, %1, %2, %3;" : "=l"(d) : "l"(a), "l"(b), "l"(c));
    return d;
}
__device__ __forceinline__ ull pk2(float lo, float hi) {
    ull d;
    asm("mov.b64 %0, {%1, %2};" : "=l"(d) : "f"(lo), "f"(hi));
    return d;
}
__device__ __forceinline__ void upk2(float& lo, float& hi, ull v) {
    asm("mov.b64 {%0, %1}, %2;" : "=f"(lo), "=f"(hi) : "l"(v));
}
__device__ __forceinline__ float ex2(float x) {
    float r;
    asm("ex2.approx.ftz.f32 %0, %1;" : "=f"(r) : "f"(x));
    return r;
}
__device__ __forceinline__ void cp_async16(unsigned int saddr, const void* gaddr) {
    asm volatile("cp.async.cg.shared.global [%0], [%1], 16;" :: "r"(saddr), "l"(gaddr));
}

__device__ __forceinline__ void codon_full(const float4* nbp, float* fullv) {
    float4 m2 = nbp[0], m1 = nbp[1], c0 = nbp[2], q1 = nbp[3], q2 = nbp[4];
    float S_c0 = c0.x + c0.y + c0.z + c0.w;
    float S_q1 = q1.x + q1.y + q1.z + q1.w;
    float S_q2 = q2.x + q2.y + q2.z + q2.w;
    float S_m1 = m1.x + m1.y + m1.z + m1.w;
    float S_m2 = m2.x + m2.y + m2.z + m2.w;
    float L_any   = S_c0 * S_q1 * S_q2 * (1.f / 64.f);
    float L_start = c0.x * q1.w * q2.z;           // ATG
    float L_ib    = 0.25f * S_c0 * q1.z * q2.w;   // NGT
    float Pall = S_m2 * S_m1 * S_c0;
    float tAA = m1.x * c0.x, tAG = m1.x * c0.z, tGA = m1.z * c0.x;
    float R_ns   = (Pall - m2.w * (tAA + tAG + tGA)) * (1.f / 61.f);
    float R_any  = Pall * (1.f / 64.f);
    float R_iep  = m2.x * m1.z * 0.25f * S_c0;    // AGN
    float R_stop = m2.w * (0.34f * tAA + 0.33f * tAG + 0.33f * tGA);
    fullv[0] = 1.f; fullv[1] = 1.f; fullv[2] = 1.f;
    fullv[3] = 1.f; fullv[4] = 1.f; fullv[5] = 1.f;
    fullv[6]  = L_any * R_ns;
    fullv[7]  = L_start * R_any;
    fullv[8]  = L_ib * R_any;
    fullv[9]  = L_ib * R_ns;
    fullv[10] = L_ib * R_any;
    fullv[11] = L_any * R_iep;
    fullv[12] = L_any * R_iep;
    fullv[13] = L_any * R_iep;
    fullv[14] = L_any * R_stop;
}

// Register-resident coefficient buffer for one dim:
// v[0..3] = A'-pairs (states 0/1..14/15), v[4..7] = B'-pairs.
struct CBuf { ulonglong2 v[8]; };

__device__ __forceinline__ void loadc(CBuf& b, const ulonglong2* p) {
#pragma unroll
    for (int h = 0; h < 8; h++) b.v[h] = p[h];
}

// One MVN dim from buffer b for positions A and B.
// aA/aB: 8 packed accumulators each = exponents for state pairs (2h, 2h+1).
__device__ __forceinline__ void fmadim(const CBuf& b, float xa, float xb,
                                       ull* aA, ull* aB) {
    ull x1a = pk2(xa, xa), x2a = pk2(xa * xa, xa * xa);
    ull x1b = pk2(xb, xb), x2b = pk2(xb * xb, xb * xb);
#pragma unroll
    for (int h = 0; h < 4; h++) {
        aA[2*h]   = fma2(b.v[h].x, x2a, fma2(b.v[4+h].x, x1a, aA[2*h]));
        aA[2*h+1] = fma2(b.v[h].y, x2a, fma2(b.v[4+h].y, x1a, aA[2*h+1]));
        aB[2*h]   = fma2(b.v[h].x, x2b, fma2(b.v[4+h].x, x1b, aB[2*h]));
        aB[2*h+1] = fma2(b.v[h].y, x2b, fma2(b.v[4+h].y, x1b, aB[2*h+1]));
    }
}

__global__ void __launch_bounds__(THREADS)
emit_kernel(const float* __restrict__ inputs,
            const float* __restrict__ eh,
            const float* __restrict__ ek,
            const float* __restrict__ eek,
            float* __restrict__ out) {
    extern __shared__ float sm[];
    const int tid = threadIdx.x;
    const int b  = blockIdx.x >> 5;
    const int p0 = (blockIdx.x & 31) << 8;

    // ---------------- phase 1: async tile load + inline prep ----------------
    const float4* in4 = (const float4*)(inputs + (size_t)(b * L_SEQ + p0) * CH);
    {
        unsigned int sbase = (unsigned int)__cvta_generic_to_shared(sm + XS_OFF);
#pragma unroll 6
        for (int i = tid; i < NPOS * CH / 4; i += THREADS)
            cp_async16(sbase + i * 16, in4 + i);
        asm volatile("cp.async.commit_group;");
    }

    const float kscale = (float)(1.4426950408889634 / 100.0); // log2(e)/TEMP
    const float basec  = (float)log(expm1(sqrt(0.05)));
    const float cconst = (float)(0.5 * 64.0 * log(2.0 * M_PI));

    // softmax rows of emission kernel -> SB[s][q]
    if (tid < 15) {
        int q = tid;
        float m = -1e30f;
        for (int s = 0; s < 15; s++) m = fmaxf(m, ek[q * 15 + s]);
        float e[15]; float sum = 0.f;
        for (int s = 0; s < 15; s++) { e[s] = expf(ek[q * 15 + s] - m); sum += e[s]; }
        float inv = 1.f / sum;
        for (int s = 0; s < 15; s++) sm[SB_OFF + s * 16 + q] = e[s] * inv;
    }
    if (tid == 15) {  // zero-pad column q=15 of SB
        for (int s = 0; s < 16; s++) sm[SB_OFF + s * 16 + 15] = 0.f;
    }
    // MVN coefficients: thread t = s*8+g handles dims 8g..8g+7 of state s
    // layout: [d][ A_0..A_15 | B_0..B_15 ]
    if (tid < 120) {
        int s = tid >> 3, g = tid & 7;
        float Cp = 0.f, ldp = 0.f;
        for (int k = 0; k < 8; k++) {
            int d = g * 8 + k;
            float mu = eek[s * 128 + d];
            float v  = eek[s * 128 + 64 + d] + basec;
            float sp = (v > 20.f) ? v : log1pf(expf(v));
            float is2 = 1.f / (sp * sp);
            sm[AB_OFF + d * 32 + s]      = -0.5f * is2 * kscale;  // A'
            sm[AB_OFF + d * 32 + 16 + s] = mu * is2 * kscale;     // B'
            Cp  = fmaf(mu * mu, is2, Cp);
            ldp += logf(sp);
        }
        sm[NB_OFF + tid * 2 + 0] = Cp;   // scratch (NB region, rebuilt later)
        sm[NB_OFF + tid * 2 + 1] = ldp;
    } else if (tid >= 120 && tid < 128) {
        // zero-pad state 15 slots
        int g = tid - 120;
        for (int k = 0; k < 8; k++) {
            int d = g * 8 + k;
            sm[AB_OFF + d * 32 + 15] = 0.f;
            sm[AB_OFF + d * 32 + 31] = 0.f;
        }
    }
    __syncthreads();
    if (tid < 15) {
        float C = 0.f, ld = 0.f;
        for (int g = 0; g < 8; g++) {
            C  += sm[NB_OFF + (tid * 8 + g) * 2 + 0];
            ld += sm[NB_OFF + (tid * 8 + g) * 2 + 1];
        }
        sm[K_OFF + tid] = (-0.5f * C - ld - cconst) * kscale;
    } else if (tid == 15) {
        sm[K_OFF + 15] = 0.f;
    }
    asm volatile("cp.async.wait_group 0;");
    __syncthreads();

    // ---------------- phase 2: nucleotide halo buffer ----------------
    float4* nb = (float4*)(sm + NB_OFF);
    for (int i = tid; i < NPOS + 4; i += THREADS) {
        int gl = p0 + i - 2;
        float4 nv;
        if (gl >= 0 && gl < L_SEQ) {
            int li = gl - p0;
            const float* nr;
            if (li >= 0 && li < NPOS) nr = sm + XS_OFF + li * CH + 79;
            else                      nr = inputs + (size_t)(b * L_SEQ + gl) * CH + 79;
            float n4 = nr[4];
            nv = make_float4(fmaf(0.25f, n4, nr[0]), fmaf(0.25f, n4, nr[1]),
                             fmaf(0.25f, n4, nr[2]), fmaf(0.25f, n4, nr[3]));
        } else {
            nv = make_float4(0.25f, 0.25f, 0.25f, 0.25f);
        }
        nb[i] = nv;
    }
    __syncthreads();

    float* rowA = sm + XS_OFF + tid * CH;
    float* rowB = rowA + 128 * CH;
    float x15A, x15B;

    // ====== phase A: class matvec + codon + hints -> staged into rows ======
    {
        float cls0[16], cls1[16];
#pragma unroll
        for (int j = 0; j < 4; j++) {
            *(float4*)(cls0 + 4 * j) = *(const float4*)(rowA + 4 * j);
            *(float4*)(cls1 + 4 * j) = *(const float4*)(rowB + 4 * j);
        }
        x15A = cls0[15]; x15B = cls1[15];
        ull ca[8], cb[8];
#pragma unroll
        for (int h = 0; h < 8; h++) { ca[h] = 0ull; cb[h] = 0ull; }
        const ulonglong2* br = (const ulonglong2*)(sm + SB_OFF);
#pragma unroll
        for (int s = 0; s < 15; s++) {
            ulonglong2 b01 = br[0], b23 = br[1], b45 = br[2], b67 = br[3];
            ull cpA = pk2(cls0[s], cls0[s]), cpB = pk2(cls1[s], cls1[s]);
            ca[0] = fma2(b01.x, cpA, ca[0]); ca[1] = fma2(b01.y, cpA, ca[1]);
            ca[2] = fma2(b23.x, cpA, ca[2]); ca[3] = fma2(b23.y, cpA, ca[3]);
            ca[4] = fma2(b45.x, cpA, ca[4]); ca[5] = fma2(b45.y, cpA, ca[5]);
            ca[6] = fma2(b67.x, cpA, ca[6]); ca[7] = fma2(b67.y, cpA, ca[7]);
            cb[0] = fma2(b01.x, cpB, cb[0]); cb[1] = fma2(b01.y, cpB, cb[1]);
            cb[2] = fma2(b23.x, cpB, cb[2]); cb[3] = fma2(b23.y, cpB, cb[3]);
            cb[4] = fma2(b45.x, cpB, cb[4]); cb[5] = fma2(b45.y, cpB, cb[5]);
            cb[6] = fma2(b67.x, cpB, cb[6]); cb[7] = fma2(b67.y, cpB, cb[7]);
            br += 4;
        }
        float clA[16], clB[16];
#pragma unroll
        for (int h = 0; h < 8; h++) {
            upk2(clA[2*h], clA[2*h+1], ca[h]);
            upk2(clB[2*h], clB[2*h+1], cb[h]);
        }
        float fullA[15], fullB[15];
        codon_full(nb + tid, fullA);
        codon_full(nb + tid + 128, fullB);
        const int glA = p0 + tid;
        const int glB = glA + 128;
        const float* hpA = nullptr;
        const float* hpB = nullptr;
        if (glA == 0)              hpA = eh + b * 30;
        else if (glA == L_SEQ - 1) hpA = eh + b * 30 + 15;
        if (glB == 0)              hpB = eh + b * 30;
        else if (glB == L_SEQ - 1) hpB = eh + b * 30 + 15;
#pragma unroll
        for (int q = 0; q < 15; q++) {
            float oA = clA[q] * fullA[q];
            float oB = clB[q] * fullB[q];
            if (hpA) oA *= hpA[q];
            if (hpB) oB *= hpB[q];
            rowA[q] = oA;
            rowB[q] = oB;
        }
    }

    // ====== phase B: MVN exponents, even-odd packed + pipelined coeffs ======
    ull aA[8], aB[8];
    {
        const ull* kp = (const ull*)(sm + K_OFF);
#pragma unroll
        for (int h = 0; h < 8; h++) { aA[h] = kp[h]; aB[h] = aA[h]; }
    }

    const ulonglong2* cdim = (const ulonglong2*)(sm + AB_OFF);
    CBuf cX, cY;

    loadc(cX, cdim); cdim += 8;                   // dim 0
    const float4* gp0 = (const float4*)(rowA + 16);   // channels 16..79
    const float4* gp1 = (const float4*)(rowB + 16);
    float4 v0 = gp0[0], v1 = gp1[0];
    loadc(cY, cdim); cdim += 8;                   // dim 1
    fmadim(cX, x15A, x15B, aA, aB);               // consume dim 0

#pragma unroll 1
    for (int j = 0; j < 15; j++) {                // dims 4j+1 .. 4j+4
        float4 n0, n1;
        if (j < 14) { n0 = gp0[1]; n1 = gp1[1]; }
        loadc(cX, cdim); cdim += 8;  fmadim(cY, v0.x, v1.x, aA, aB);
        loadc(cY, cdim); cdim += 8;  fmadim(cX, v0.y, v1.y, aA, aB);
        loadc(cX, cdim); cdim += 8;  fmadim(cY, v0.z, v1.z, aA, aB);
        loadc(cY, cdim); cdim += 8;  fmadim(cX, v0.w, v1.w, aA, aB);
        gp0 += 1; gp1 += 1;
        if (j < 14) { v0 = n0; v1 = n1; }
    }
    // tail: after loop cY holds dim 61, cdim -> dim 62.
    // RELOAD channels 76..79 (gp0/gp1 now point there; v0/v1 are stale).
    {
        float4 t0 = gp0[0], t1 = gp1[0];
        loadc(cX, cdim); cdim += 8;  fmadim(cY, t0.x, t1.x, aA, aB);  // dim 61
        loadc(cY, cdim);             fmadim(cX, t0.y, t1.y, aA, aB);  // dim 62
        fmadim(cY, t0.z, t1.z, aA, aB);                               // dim 63
    }

    // epilogue: unpack paired exponents, multiply staged values
#pragma unroll
    for (int h = 0; h < 8; h++) {
        float e0, e1;
        upk2(e0, e1, aA[h]);
        rowA[2*h] *= ex2(e0);
        if (h < 7) rowA[2*h+1] *= ex2(e1);
        upk2(e0, e1, aB[h]);
        rowB[2*h] *= ex2(e0);
        if (h < 7) rowB[2*h+1] *= ex2(e1);
    }
    __syncthreads();

    // coalesced flush (incremental pos/q, no divisions)
    float* og = out + (size_t)(b * L_SEQ + p0) * 15;
    int pos = tid / 15;
    int q   = tid - pos * 15;
#pragma unroll 6
    for (int i = tid; i < NPOS * 15; i += THREADS) {
        og[i] = sm[XS_OFF + pos * CH + q];
        pos += 8; q += 8;
        if (q >= 15) { q -= 15; pos += 1; }
    }
}

extern "C" void kernel_launch(void* const* d_in, const int* in_sizes, int n_in,
                              void* d_out, int out_size) {
    const float *inp = nullptr, *eh = nullptr, *ek = nullptr, *eek = nullptr;
    for (int i = 0; i < n_in; i++) {
        switch (in_sizes[i]) {
            case 11010048: inp = (const float*)d_in[i]; break; // inputs
            case 480:      eh  = (const float*)d_in[i]; break; // end_hints
            case 225:      ek  = (const float*)d_in[i]; break; // emission_kernel
            case 1920:     eek = (const float*)d_in[i]; break; // embedding_emission_kernel
        }
    }
    float* out = (float*)d_out;

    cudaFuncSetAttribute(emit_kernel, cudaFuncAttributeMaxDynamicSharedMemorySize,
                         SMEM_BYTES);

    emit_kernel<<<(B_SEQ * L_SEQ) / NPOS, THREADS, SMEM_BYTES>>>(inp, eh, ek, eek, out);
}